// round 10
// baseline (speedup 1.0000x reference)
#include <cuda_runtime.h>
#include <cuda_bf16.h>
#include <cuda_pipeline_primitives.h>
#include <cstdint>

#define CC      2048
#define HW      49
#define SIDE    7
#define NTHR    512
#define GRID    304                  // 2 CTAs per SM on 152 SMs
#define SPLIT   16                   // units per image
#define CHC     (CC / SPLIT)         // 128 channels per unit
#define UNIT_FLOATS (CHC * HW)       // 6272 floats = 25088 B (contiguous in x)
#define UNIT_CPY16  (UNIT_FLOATS/4)  // 1568 x 16B cp.async per unit
#define NMAX    256
#define NUNITS  (NMAX * SPLIT)       // 4096

// scratch: [n][sp][p][3]  = {sum, d0, d1}
__device__ float g_scratch[NMAX * SPLIT * HW * 3];
__device__ int   g_count[NMAX];      // zero-init; epilogue resets its slot

struct Smem {
    float2 w2sh[CC];                 // full W2 table {W2_0, W2_1}: 16 KB
    float  buf[2][UNIT_FLOATS];      // double buffer: 50176 B
    float  acc[8][HW][3];            // 4704 B
    float  fin[HW][3];
    float  gaps[HW];
    float  dls[HW];
    float  red[16][2];
    float  s_a0, s_a1, s_gmean;
    int    s_idx, s_last;
};

__device__ __forceinline__ void issue_unit(Smem* sm, int b, const float* x,
                                           int u, int tid) {
    // unit u occupies x[u*UNIT_FLOATS .. +UNIT_FLOATS) (contiguous, 16B aligned)
    const float4* src = (const float4*)(x + (size_t)u * UNIT_FLOATS);
    float4*       dst = (float4*)sm->buf[b];
    for (int i = tid; i < UNIT_CPY16; i += NTHR)
        __pipeline_memcpy_async(dst + i, src + i, 16);
    __pipeline_commit();
}

__global__ __launch_bounds__(NTHR, 2)
void rpcp_persist_kernel(const float* __restrict__ x,
                         const float* __restrict__ Wlin,
                         const float* __restrict__ bias,
                         float* __restrict__ out,
                         float* __restrict__ scratch)
{
    extern __shared__ char dynsm[];
    Smem* sm = (Smem*)dynsm;

    const int tid = threadIdx.x;
    const int p   = tid & 63;        // 0..48 active
    const int cg  = tid >> 6;        // 0..7

    // one-time: full W2 table {W2_0[c], W2_1[c]}
    for (int c = tid; c < CC; c += NTHR)
        sm->w2sh[c] = make_float2(__ldg(Wlin + CC + c), __ldg(Wlin + 3*CC + c));

    // prologue prefetch
    issue_unit(sm, 0, x, blockIdx.x, tid);

    int b = 0;
    for (int u = blockIdx.x; u < NUNITS; u += GRID, b ^= 1) {
        // prefetch next unit into other buffer while this one computes
        if (u + GRID < NUNITS) {
            issue_unit(sm, b ^ 1, x, u + GRID, tid);
            __pipeline_wait_prior(1);      // unit u's group done
        } else {
            __pipeline_wait_prior(0);
        }
        __syncthreads();                   // buf[b] visible to all threads

        const int n  = u >> 4;             // SPLIT = 16
        const int sp = u & 15;

        if (p < HW) {
            float s = 0.f, d0 = 0.f, d1 = 0.f;
            const float*  bb   = sm->buf[b];
            const float2* wrow = &sm->w2sh[sp * CHC];
            #pragma unroll
            for (int k = 0; k < CHC / 8; k++) {     // 16 channels per thread
                const int c = cg + k * 8;
                const float  v = bb[c * HW + p];    // conflict-free LDS
                const float2 w = wrow[c];           // warp-uniform broadcast
                s  += v;
                d0 = fmaf(v, w.x, d0);
                d1 = fmaf(v, w.y, d1);
            }
            sm->acc[cg][p][0] = s;
            sm->acc[cg][p][1] = d0;
            sm->acc[cg][p][2] = d1;
        }
        __syncthreads();

        if (tid < HW * 3) {
            const int pp = tid / 3, k = tid % 3;
            float t = 0.f;
            #pragma unroll
            for (int g = 0; g < 8; g++) t += sm->acc[g][pp][k];
            scratch[(u * HW + pp) * 3 + k] = t;
        }
        __syncthreads();

        if (tid == 0) {
            __threadfence();                        // release (cumulative via bar)
            int old = atomicAdd(&g_count[n], 1);
            sm->s_last = (old == SPLIT - 1);
            if (sm->s_last) __threadfence();        // acquire
        }
        __syncthreads();

        if (sm->s_last) {
            // ---- epilogue for image n (overlaps other CTAs' streaming) ----
            if (tid < HW * 3) {
                const int pp = tid / 3, k = tid % 3;
                float t = 0.f;
                #pragma unroll
                for (int g = 0; g < SPLIT; g++)
                    t += scratch[(((n << 4) + g) * HW + pp) * 3 + k];
                sm->fin[pp][k] = t;
            }
            __syncthreads();

            // warp argmax over channel-sum (first occurrence on ties)
            if (tid < 32) {
                float v  = sm->fin[tid][0];
                int   bi = tid;
                if (tid + 32 < HW) {
                    float v2 = sm->fin[tid + 32][0];
                    if (v2 > v) { v = v2; bi = tid + 32; }
                }
                #pragma unroll
                for (int off = 16; off > 0; off >>= 1) {
                    float ov = __shfl_down_sync(0xffffffffu, v,  off);
                    int   oi = __shfl_down_sync(0xffffffffu, bi, off);
                    if (ov > v || (ov == v && oi < bi)) { v = ov; bi = oi; }
                }
                if (tid == 0) { sm->s_idx = bi; g_count[n] = 0; }
            }
            __syncthreads();
            const int idx = sm->s_idx;

            // a0,a1 = dot(x[n,:,idx], W1_{0,1}) — re-read single column
            {
                float a0 = 0.f, a1 = 0.f;
                const float* xn = x + (size_t)n * CC * HW;
                #pragma unroll
                for (int k = 0; k < CC / NTHR; k++) {
                    const int c = tid + k * NTHR;
                    const float v = __ldg(xn + (size_t)c * HW + idx);
                    a0 = fmaf(v, __ldg(Wlin + c),          a0);
                    a1 = fmaf(v, __ldg(Wlin + 2*CC + c),   a1);
                }
                #pragma unroll
                for (int off = 16; off > 0; off >>= 1) {
                    a0 += __shfl_down_sync(0xffffffffu, a0, off);
                    a1 += __shfl_down_sync(0xffffffffu, a1, off);
                }
                if ((tid & 31) == 0) {
                    sm->red[tid >> 5][0] = a0;
                    sm->red[tid >> 5][1] = a1;
                }
            }
            __syncthreads();
            if (tid < 32) {
                float r0 = (tid < 16) ? sm->red[tid][0] : 0.f;
                float r1 = (tid < 16) ? sm->red[tid][1] : 0.f;
                #pragma unroll
                for (int off = 8; off > 0; off >>= 1) {
                    r0 += __shfl_down_sync(0xffffffffu, r0, off);
                    r1 += __shfl_down_sync(0xffffffffu, r1, off);
                }
                if (tid == 0) { sm->s_a0 = r0; sm->s_a1 = r1; }
            }
            __syncthreads();

            if (tid < HW) {
                float pr0 = sm->fin[tid][1] + sm->s_a0 + __ldg(bias + 0);
                float pr1 = sm->fin[tid][2] + sm->s_a1 + __ldg(bias + 1);
                pr0 = fmaxf(pr0, 0.f);
                pr1 = fmaxf(pr1, 0.f);
                if (tid == idx) { pr0 = 0.f; pr1 = 0.f; }

                const float ri = (float)(tid / SIDE - idx / SIDE) * (1.f / (float)SIDE);
                const float rj = (float)(tid % SIDE - idx % SIDE) * (1.f / (float)SIDE);
                const float rd = sqrtf(ri * ri + rj * rj);
                const float ang = (atan2f(rj, ri) * (1.f / 3.14159265358979323846f) + 1.f) * 0.5f;

                float dl = pr0 - rd; dl *= dl;
                float g  = pr1 - ang;
                if (g < 0.f) g += 1.f;
                sm->gaps[tid] = g;
                sm->dls[tid]  = dl;
            }
            __syncthreads();

            if (tid < 32) {
                float t = (tid < HW) ? sm->gaps[tid] : 0.f;
                if (tid + 32 < HW) t += sm->gaps[tid + 32];
                #pragma unroll
                for (int off = 16; off > 0; off >>= 1)
                    t += __shfl_down_sync(0xffffffffu, t, off);
                if (tid == 0) sm->s_gmean = t * (1.f / (float)HW);
            }
            __syncthreads();

            if (tid < HW) {
                float g = sm->gaps[tid] - sm->s_gmean;
                out[n * HW + tid] = sm->dls[tid] + g * g;
            }
            __syncthreads();
        }
    }
}

extern "C" void kernel_launch(void* const* d_in, const int* in_sizes, int n_in,
                              void* d_out, int out_size)
{
    const float* x    = (const float*)d_in[0];
    const float* Wlin = (const float*)d_in[1];
    const float* b    = (const float*)d_in[2];
    float*       out  = (float*)d_out;

    float* scratch = nullptr;
    cudaGetSymbolAddress((void**)&scratch, g_scratch);

    // >48KB dynamic smem requires opt-in (idempotent; no allocation involved)
    cudaFuncSetAttribute(rpcp_persist_kernel,
                         cudaFuncAttributeMaxDynamicSharedMemorySize,
                         (int)sizeof(Smem));

    rpcp_persist_kernel<<<GRID, NTHR, sizeof(Smem)>>>(x, Wlin, b, out, scratch);
}

// round 11
// speedup vs baseline: 2.6939x; 2.6939x over previous
#include <cuda_runtime.h>
#include <cuda_bf16.h>
#include <cstdint>

#define CC      2048
#define HW      49
#define SIDE    7
#define CGROUPS 8
#define NTHR    512
#define SPLIT   16
#define CHC     (CC / SPLIT)      // 128 channels per CTA
#define NMAX    256

// scratch: [n][sp][p][3] = {sum, d0, d1}
__device__ float g_scratch[NMAX * SPLIT * HW * 3];

// ---------------- K1: lean streaming partial ----------------
__global__ __launch_bounds__(NTHR, 3)
void rpcp_partial_kernel(const float* __restrict__ x,
                         const float* __restrict__ Wlin,
                         float* __restrict__ scratch)
{
    __shared__ float2 wsh[CHC];               // {W2_0, W2_1} slice: 1 KB
    __shared__ float  acc[CGROUPS][HW][3];

    const int tid = threadIdx.x;
    const int u   = blockIdx.x;               // unit id
    const int n   = u >> 4;                   // SPLIT = 16
    const int sp  = u & 15;
    const int c0  = sp * CHC;

    for (int c = tid; c < CHC; c += NTHR) {
        const int cc = c0 + c;
        wsh[c] = make_float2(Wlin[CC + cc], Wlin[3 * CC + cc]);  // W2 rows
    }
    __syncthreads();

    const int p  = tid & 63;     // 0..48 active
    const int cg = tid >> 6;     // 0..7

    if (p < HW) {
        float s = 0.f, d0 = 0.f, d1 = 0.f;
        const float* xp = x + (size_t)n * CC * HW + (size_t)c0 * HW + p;
        #pragma unroll 8
        for (int c = cg; c < CHC; c += CGROUPS) {   // exactly 16 iterations
            const float  v = __ldg(xp + c * HW);    // coalesced across lanes
            const float2 w = wsh[c];                // warp-uniform broadcast
            s  += v;
            d0 = fmaf(v, w.x, d0);
            d1 = fmaf(v, w.y, d1);
        }
        acc[cg][p][0] = s;  acc[cg][p][1] = d0;  acc[cg][p][2] = d1;
    }
    __syncthreads();

    if (tid < HW * 3) {
        const int pp = tid / 3, k = tid % 3;
        float t = 0.f;
        #pragma unroll
        for (int g = 0; g < CGROUPS; g++) t += acc[g][pp][k];
        scratch[(u * HW + pp) * 3 + k] = t;
    }
}

// ---------------- K2: per-image reduce + epilogue ----------------
__global__ __launch_bounds__(NTHR, 3)
void rpcp_final_kernel(const float* __restrict__ x,
                       const float* __restrict__ Wlin,
                       const float* __restrict__ bias,
                       const float* __restrict__ scratch,
                       float* __restrict__ out)
{
    __shared__ float fin[HW][3];   // {sum, d0, d1}
    __shared__ float gaps[HW];
    __shared__ float dls[HW];
    __shared__ float red[16][2];
    __shared__ float s_a0, s_a1, s_gmean;
    __shared__ int   s_idx;

    const int n   = blockIdx.x;
    const int tid = threadIdx.x;

    if (tid < HW * 3) {
        const int pp = tid / 3, k = tid % 3;
        float t = 0.f;
        #pragma unroll
        for (int g = 0; g < SPLIT; g++)
            t += scratch[(((n << 4) + g) * HW + pp) * 3 + k];
        fin[pp][k] = t;
    }
    __syncthreads();

    // warp argmax over channel-sum (first occurrence on ties)
    if (tid < 32) {
        float v  = fin[tid][0];
        int   bi = tid;
        if (tid + 32 < HW) {
            float v2 = fin[tid + 32][0];
            if (v2 > v) { v = v2; bi = tid + 32; }
        }
        #pragma unroll
        for (int off = 16; off > 0; off >>= 1) {
            float ov = __shfl_down_sync(0xffffffffu, v,  off);
            int   oi = __shfl_down_sync(0xffffffffu, bi, off);
            if (ov > v || (ov == v && oi < bi)) { v = ov; bi = oi; }
        }
        if (tid == 0) s_idx = bi;
    }
    __syncthreads();
    const int idx = s_idx;

    // a0,a1 = dot(x[n,:,idx], W1_{0,1}) — re-read the single argmax column
    {
        float a0 = 0.f, a1 = 0.f;
        const float* xn = x + (size_t)n * CC * HW;
        #pragma unroll
        for (int k = 0; k < CC / NTHR; k++) {       // 4 channels per thread
            const int c = tid + k * NTHR;
            const float v = __ldg(xn + (size_t)c * HW + idx);
            a0 = fmaf(v, __ldg(Wlin + c),        a0);
            a1 = fmaf(v, __ldg(Wlin + 2*CC + c), a1);
        }
        #pragma unroll
        for (int off = 16; off > 0; off >>= 1) {
            a0 += __shfl_down_sync(0xffffffffu, a0, off);
            a1 += __shfl_down_sync(0xffffffffu, a1, off);
        }
        if ((tid & 31) == 0) { red[tid >> 5][0] = a0; red[tid >> 5][1] = a1; }
    }
    __syncthreads();
    if (tid < 32) {
        float r0 = (tid < 16) ? red[tid][0] : 0.f;
        float r1 = (tid < 16) ? red[tid][1] : 0.f;
        #pragma unroll
        for (int off = 8; off > 0; off >>= 1) {
            r0 += __shfl_down_sync(0xffffffffu, r0, off);
            r1 += __shfl_down_sync(0xffffffffu, r1, off);
        }
        if (tid == 0) { s_a0 = r0; s_a1 = r1; }
    }
    __syncthreads();

    if (tid < HW) {
        float pr0 = fin[tid][1] + s_a0 + __ldg(bias + 0);
        float pr1 = fin[tid][2] + s_a1 + __ldg(bias + 1);
        pr0 = fmaxf(pr0, 0.f);
        pr1 = fmaxf(pr1, 0.f);
        if (tid == idx) { pr0 = 0.f; pr1 = 0.f; }

        const float ri = (float)(tid / SIDE - idx / SIDE) * (1.f / (float)SIDE);
        const float rj = (float)(tid % SIDE - idx % SIDE) * (1.f / (float)SIDE);
        const float rd = sqrtf(ri * ri + rj * rj);
        const float ang = (atan2f(rj, ri) * (1.f / 3.14159265358979323846f) + 1.f) * 0.5f;

        float dl = pr0 - rd; dl *= dl;
        float g  = pr1 - ang;
        if (g < 0.f) g += 1.f;
        gaps[tid] = g;
        dls[tid]  = dl;
    }
    __syncthreads();

    if (tid < 32) {
        float t = (tid < HW) ? gaps[tid] : 0.f;
        if (tid + 32 < HW) t += gaps[tid + 32];
        #pragma unroll
        for (int off = 16; off > 0; off >>= 1)
            t += __shfl_down_sync(0xffffffffu, t, off);
        if (tid == 0) s_gmean = t * (1.f / (float)HW);
    }
    __syncthreads();

    if (tid < HW) {
        float g = gaps[tid] - s_gmean;
        out[n * HW + tid] = dls[tid] + g * g;
    }
}

extern "C" void kernel_launch(void* const* d_in, const int* in_sizes, int n_in,
                              void* d_out, int out_size)
{
    const float* x    = (const float*)d_in[0];
    const float* Wlin = (const float*)d_in[1];
    const float* b    = (const float*)d_in[2];
    float*       out  = (float*)d_out;

    const int N = in_sizes[0] / (CC * HW);   // 256

    float* scratch = nullptr;
    cudaGetSymbolAddress((void**)&scratch, g_scratch);

    rpcp_partial_kernel<<<N * SPLIT, NTHR>>>(x, Wlin, scratch);
    rpcp_final_kernel<<<N, NTHR>>>(x, Wlin, b, scratch, out);
}